// round 3
// baseline (speedup 1.0000x reference)
#include <cuda_runtime.h>

#define NTOK 8192
#define DIM 128
#define ODIM 128
#define OT 8
#define THREADS 256

typedef unsigned long long u64;

__device__ __forceinline__ float2 ffma2(float2 a, float2 b, float2 c) {
    float2 d;
    asm("fma.rn.f32x2 %0, %1, %2, %3;"
        : "=l"(reinterpret_cast<u64&>(d))
        : "l"(reinterpret_cast<u64 const&>(a)),
          "l"(reinterpret_cast<u64 const&>(b)),
          "l"(reinterpret_cast<u64 const&>(c)));
    return d;
}
__device__ __forceinline__ float2 fmul2(float2 a, float2 b) {
    float2 d;
    asm("mul.rn.f32x2 %0, %1, %2;"
        : "=l"(reinterpret_cast<u64&>(d))
        : "l"(reinterpret_cast<u64 const&>(a)),
          "l"(reinterpret_cast<u64 const&>(b)));
    return d;
}
__device__ __forceinline__ float ex2f(float a) {
    float r; asm("ex2.approx.ftz.f32 %0, %1;" : "=f"(r) : "f"(a)); return r;
}

// Math:
//   s = softplus(scale)+0.1, z=(xn-t)/s, H=0.5*log2(e)=0.72134752
//   nu = -H z^2 = a*xn^2 + b*xn + c  with a=-H/s^2, b=-2at, c=a t^2
//   wavelet term = C*ww*(z^2-1)*exp(-z^2/2); note (z^2-1) = -(nu+H)/H
//   with m = nu+H:  term = C'* m * 2^m,  C' = -(C/H)*2^(-H)*ww = -0.72927235*ww
//   m = fma(xsq, a, fma(xn, b, cm)),  cm = c + H
__global__ __launch_bounds__(THREADS, 3)
void wavekan_fused(const float* __restrict__ x,
                   const float* __restrict__ scale,
                   const float* __restrict__ trans,
                   const float* __restrict__ ww,
                   const float* __restrict__ bw,
                   const float* __restrict__ gamma,
                   const float* __restrict__ beta,
                   float* __restrict__ out) {
    __shared__ float4 sA [OT][DIM / 4];   // a
    __shared__ float4 sB [OT][DIM / 4];   // b
    __shared__ float4 sCM[OT][DIM / 4];   // cm
    __shared__ float4 sCP[OT][DIM / 4];   // C'
    __shared__ float4 sW [OT][DIM / 4];   // base_w
    __shared__ float4 sG [DIM / 4];
    __shared__ float4 sBt[DIM / 4];

    const int o0 = blockIdx.y * OT;
    const int tid = threadIdx.x;
    const float H = 0.72134752f;

    // ---- fold params for this o-tile into smem ----
    #pragma unroll
    for (int k = 0; k < (OT * DIM) / THREADS; k++) {
        int i = tid + k * THREADS;
        int gi = o0 * DIM + i;
        float sc = scale[gi];
        float sp = (sc > 20.0f) ? sc : log1pf(expf(sc));
        float s = sp + 0.1f;
        float a = -H / (s * s);
        float t = trans[gi];
        ((float*)sA)[i]  = a;
        ((float*)sB)[i]  = -2.0f * a * t;
        ((float*)sCM)[i] = fmaf(a * t, t, H);
        ((float*)sCP)[i] = -0.72927235f * ww[gi];
        ((float*)sW)[i]  = bw[gi];
    }
    if (tid < DIM / 4) {
        sG[tid]  = ((const float4*)gamma)[tid];
        sBt[tid] = ((const float4*)beta)[tid];
    }

    // ---- per-thread LayerNorm stats for token n ----
    const int n = blockIdx.x * THREADS + tid;
    const float4* xr4 = (const float4*)(x + (size_t)n * DIM);
    float sm = 0.0f, sq = 0.0f;
    #pragma unroll 4
    for (int dc = 0; dc < DIM / 4; dc++) {
        float4 v = xr4[dc];
        sm += (v.x + v.y) + (v.z + v.w);
        sq += (v.x * v.x + v.y * v.y) + (v.z * v.z + v.w * v.w);
    }
    float mu = sm * (1.0f / DIM);
    float var = fmaf(-mu, mu, sq * (1.0f / DIM));
    float rst = rsqrtf(var + 1e-5f);

    __syncthreads();

    const float2 r2   = make_float2(rst, rst);
    const float2 nmu2 = make_float2(-mu, -mu);

    float2 accw[OT], accb[OT];
    #pragma unroll
    for (int o = 0; o < OT; o++) {
        accw[o] = make_float2(0.0f, 0.0f);
        accb[o] = make_float2(0.0f, 0.0f);
    }

    for (int dc = 0; dc < DIM / 4; dc++) {
        float4 xv = xr4[dc];               // L1-resident
        float4 g4 = sG[dc];
        float4 b4 = sBt[dc];
        float2 x_lo = make_float2(xv.x, xv.y);
        float2 x_hi = make_float2(xv.z, xv.w);
        // xn = x*(r*g) + (beta - mu*r*g)
        float2 rg_lo = fmul2(make_float2(g4.x, g4.y), r2);
        float2 rg_hi = fmul2(make_float2(g4.z, g4.w), r2);
        float2 xn_lo = ffma2(x_lo, rg_lo, ffma2(rg_lo, nmu2, make_float2(b4.x, b4.y)));
        float2 xn_hi = ffma2(x_hi, rg_hi, ffma2(rg_hi, nmu2, make_float2(b4.z, b4.w)));
        float2 xq_lo = fmul2(xn_lo, xn_lo);
        float2 xq_hi = fmul2(xn_hi, xn_hi);

        #pragma unroll
        for (int o = 0; o < OT; o++) {
            float4 A4  = sA [o][dc];
            float4 B4  = sB [o][dc];
            float4 CM4 = sCM[o][dc];
            float4 CP4 = sCP[o][dc];
            float4 W4  = sW [o][dc];
            // low pair
            {
                float2 m = ffma2(xq_lo, make_float2(A4.x, A4.y),
                                 ffma2(xn_lo, make_float2(B4.x, B4.y),
                                       make_float2(CM4.x, CM4.y)));
                float2 e = make_float2(ex2f(m.x), ex2f(m.y));
                float2 t = fmul2(m, e);
                accw[o] = ffma2(t, make_float2(CP4.x, CP4.y), accw[o]);
            }
            // high pair
            {
                float2 m = ffma2(xq_hi, make_float2(A4.z, A4.w),
                                 ffma2(xn_hi, make_float2(B4.z, B4.w),
                                       make_float2(CM4.z, CM4.w)));
                float2 e = make_float2(ex2f(m.x), ex2f(m.y));
                float2 t = fmul2(m, e);
                accw[o] = ffma2(t, make_float2(CP4.z, CP4.w), accw[o]);
            }
            // base GEMM (packed)
            accb[o] = ffma2(x_lo, make_float2(W4.x, W4.y), accb[o]);
            accb[o] = ffma2(x_hi, make_float2(W4.z, W4.w), accb[o]);
        }
    }

    // ---- epilogue: out = wavelet + silu(base) ----
    float* op = out + (size_t)n * ODIM + o0;
    #pragma unroll
    for (int ob = 0; ob < OT / 4; ob++) {
        float4 res;
        float* rp = (float*)&res;
        #pragma unroll
        for (int j = 0; j < 4; j++) {
            int o = ob * 4 + j;
            float b = accb[o].x + accb[o].y;
            float t = ex2f(-1.44269504f * b);
            float sig = __frcp_rn(1.0f + t);
            rp[j] = fmaf(b, sig, accw[o].x + accw[o].y);
        }
        ((float4*)op)[ob] = res;
    }
}

extern "C" void kernel_launch(void* const* d_in, const int* in_sizes, int n_in,
                              void* d_out, int out_size) {
    const float* x     = (const float*)d_in[0];
    const float* scale = (const float*)d_in[1];
    const float* trans = (const float*)d_in[2];
    const float* ww    = (const float*)d_in[3];
    const float* bw    = (const float*)d_in[4];
    const float* gamma = (const float*)d_in[5];
    const float* beta  = (const float*)d_in[6];
    float* out = (float*)d_out;

    dim3 grid(NTOK / THREADS, ODIM / OT);
    wavekan_fused<<<grid, THREADS>>>(x, scale, trans, ww, bw, gamma, beta, out);
}